// round 16
// baseline (speedup 1.0000x reference)
#include <cuda_runtime.h>
#include <cuda_bf16.h>
#include <math.h>
#include <stdint.h>

// Problem constants
#define BB 32
#define TT 577
#define EE 1024
#define HH 16
#define DD 64
#define MM (BB * TT)   // 18464 rows

// Scratch (alloc-free rule: __device__ globals)
__device__ __nv_bfloat16 g_xh[(size_t)MM * EE];
__device__ __nv_bfloat16 g_xl[(size_t)MM * EE];
__device__ __nv_bfloat16 g_qh[(size_t)MM * EE];
__device__ __nv_bfloat16 g_ql[(size_t)MM * EE];
__device__ __nv_bfloat16 g_kh[(size_t)MM * EE];
__device__ __nv_bfloat16 g_kl[(size_t)MM * EE];
__device__ __nv_bfloat16 g_vh[(size_t)MM * EE];
__device__ __nv_bfloat16 g_vl[(size_t)MM * EE];
__device__ __nv_bfloat16 g_ah[(size_t)MM * EE];
__device__ __nv_bfloat16 g_al[(size_t)MM * EE];
__device__ __nv_bfloat16 g_wth[(size_t)4 * EE * EE];   // W^T hi, [n][k]
__device__ __nv_bfloat16 g_wtl[(size_t)4 * EE * EE];   // W^T lo

// ---------------------------------------------------------------------------
// common helpers
// ---------------------------------------------------------------------------
__device__ __forceinline__ uint32_t smem_u32(const void* p) {
    return (uint32_t)__cvta_generic_to_shared(p);
}
__device__ __forceinline__ void cp16(uint32_t dst, const void* src, bool pred) {
    asm volatile("cp.async.cg.shared.global [%0], [%1], 16, %2;\n"
                 :: "r"(dst), "l"(src), "r"(pred ? 16 : 0));
}
#define CP_COMMIT() asm volatile("cp.async.commit_group;\n" ::: "memory")
#define CP_WAIT0()  asm volatile("cp.async.wait_group 0;\n" ::: "memory")

// pack_bf16(a, b) -> u32 with a in the LOW half (memory-first element)
__device__ __forceinline__ uint32_t pack_bf16(float lo, float hi) {
    uint32_t r;
    asm("cvt.rn.bf16x2.f32 %0, %1, %2;" : "=r"(r) : "f"(hi), "f"(lo));
    return r;
}
__device__ __forceinline__ float bf16lo_f(uint32_t p) { return __uint_as_float(p << 16); }
__device__ __forceinline__ float bf16hi_f(uint32_t p) { return __uint_as_float(p & 0xffff0000u); }

// bf16 m16n8k16 MMA (A row-major, B col-major i.e. [N][K])
__device__ __forceinline__ void mma_bf16(float* acc,
                                         uint32_t a0, uint32_t a1, uint32_t a2, uint32_t a3,
                                         uint32_t b0, uint32_t b1) {
    asm volatile(
        "mma.sync.aligned.m16n8k16.row.col.f32.bf16.bf16.f32 "
        "{%0,%1,%2,%3}, {%4,%5,%6,%7}, {%8,%9}, {%0,%1,%2,%3};\n"
        : "+f"(acc[0]), "+f"(acc[1]), "+f"(acc[2]), "+f"(acc[3])
        : "r"(a0), "r"(a1), "r"(a2), "r"(a3), "r"(b0), "r"(b1));
}

// ---------------------------------------------------------------------------
// prep kernels: fp32 -> bf16 hi/lo splits
// ---------------------------------------------------------------------------
__global__ void prep_x(const float* __restrict__ x,
                       __nv_bfloat16* __restrict__ xh,
                       __nv_bfloat16* __restrict__ xl, int n4) {
    int idx = blockIdx.x * 256 + threadIdx.x;
    if (idx >= n4) return;
    float4 v = ((const float4*)x)[idx];
    uint32_t h0 = pack_bf16(v.x, v.y);
    uint32_t h1 = pack_bf16(v.z, v.w);
    uint32_t l0 = pack_bf16(v.x - bf16lo_f(h0), v.y - bf16hi_f(h0));
    uint32_t l1 = pack_bf16(v.z - bf16lo_f(h1), v.w - bf16hi_f(h1));
    ((uint2*)xh)[idx] = make_uint2(h0, h1);
    ((uint2*)xl)[idx] = make_uint2(l0, l1);
}

// transpose + split: W[k][n] fp32 -> Wt_h/Wt_l [n][k] bf16 (64x64 tiles)
// stride 68 (272 B = 17*16) keeps the float4 staging stores 16B-aligned.
__global__ __launch_bounds__(256) void prep_w(const float* __restrict__ W,
                                              __nv_bfloat16* __restrict__ wth,
                                              __nv_bfloat16* __restrict__ wtl) {
    __shared__ float s[64][68];
    const int tid = threadIdx.x;
    const int k0 = blockIdx.y * 64, n0 = blockIdx.x * 64;
    #pragma unroll
    for (int i = 0; i < 4; i++) {
        const int idx = tid + i * 256;
        const int kk = idx >> 4;
        const int n4 = (idx & 15) * 4;
        *(float4*)&s[kk][n4] = *(const float4*)(W + (size_t)(k0 + kk) * EE + n0 + n4);
    }
    __syncthreads();
    #pragma unroll
    for (int i = 0; i < 4; i++) {
        const int idx = tid + i * 256;
        const int nn = idx >> 4;
        const int k4 = (idx & 15) * 4;
        float s0 = s[k4 + 0][nn], s1 = s[k4 + 1][nn];
        float s2 = s[k4 + 2][nn], s3 = s[k4 + 3][nn];
        uint32_t h0 = pack_bf16(s0, s1), h1 = pack_bf16(s2, s3);
        uint32_t l0 = pack_bf16(s0 - bf16lo_f(h0), s1 - bf16hi_f(h0));
        uint32_t l1 = pack_bf16(s2 - bf16lo_f(h1), s3 - bf16hi_f(h1));
        const size_t off = (size_t)(n0 + nn) * EE + k0 + k4;
        *(uint2*)(wth + off) = make_uint2(h0, h1);
        *(uint2*)(wtl + off) = make_uint2(l0, l1);
    }
}

// ---------------------------------------------------------------------------
// GEMM (3xBF16, mma.sync m16n8k16): C = A @ W + bias
// Output either fp32 (obf=0, Cf) or bf16 hi/lo pairs (obf=1, ch/cl).
// Block tile 128x256, BK=32 elems, 8 warps (2x4), warp tile 64x64.
// smem: packed bf16 (u32), row stride 20 u32. 122880 B, 1 CTA/SM.
// ---------------------------------------------------------------------------
#define GBN 256
#define GKA 2560     // u32 per A hi/lo buffer (128 rows x 20)
#define GKB 5120     // u32 per B hi/lo buffer (256 rows x 20)
#define GBUF (2 * GKA + 2 * GKB)   // 15360 u32 per stage
#define GSMEM_B (2 * GBUF * 4)     // 122880 bytes

__global__ __launch_bounds__(256, 1) void gemm_bf16x3(
    const __nv_bfloat16* __restrict__ agh, const __nv_bfloat16* __restrict__ agl,
    const __nv_bfloat16* __restrict__ bgh, const __nv_bfloat16* __restrict__ bgl,
    const float* __restrict__ bias, float* __restrict__ Cf,
    __nv_bfloat16* __restrict__ ch, __nv_bfloat16* __restrict__ cl,
    int obf, int M)
{
    extern __shared__ uint32_t su[];
    const uint32_t sbase = smem_u32(su);

    const int tid  = threadIdx.x;
    const int lane = tid & 31;
    const int wid  = tid >> 5;        // 0..7
    const int g    = lane >> 2;       // 0..7
    const int tg   = lane & 3;        // 0..3
    const int wm   = (wid >> 2) * 64; // warp row offset (0/64)
    const int wn   = (wid & 3) * 64;  // warp col offset (0/64/128/192)
    const int rowBase = blockIdx.y * 128;
    const int colBase = blockIdx.x * GBN;

    float acc[4][8][4];
    #pragma unroll
    for (int mf = 0; mf < 4; mf++)
        #pragma unroll
        for (int nf = 0; nf < 8; nf++)
            #pragma unroll
            for (int c = 0; c < 4; c++) acc[mf][nf][c] = 0.f;

    auto stage = [&](int buf, int k0) {   // k0 in bf16 elements
        const uint32_t b0 = sbase + (uint32_t)buf * GBUF * 4;
        #pragma unroll
        for (int i = 0; i < 2; i++) {
            const int idx = tid + i * 256;
            const int r = idx >> 2;
            const int c = idx & 3;
            const bool pred = (rowBase + r) < M;
            const size_t go = (size_t)(rowBase + r) * EE + k0 + c * 8;
            const uint32_t dst = b0 + (uint32_t)(r * 20 + c * 4) * 4;
            cp16(dst, agh + go, pred);
            cp16(dst + GKA * 4, agl + go, pred);
        }
        #pragma unroll
        for (int i = 0; i < 4; i++) {
            const int idx = tid + i * 256;
            const int n = idx >> 2;
            const int c = idx & 3;
            const size_t go = (size_t)(colBase + n) * EE + k0 + c * 8;
            const uint32_t dst = b0 + (uint32_t)(2 * GKA + n * 20 + c * 4) * 4;
            cp16(dst, bgh + go, true);
            cp16(dst + GKB * 4, bgl + go, true);
        }
        CP_COMMIT();
    };

    stage(0, 0);
    CP_WAIT0();
    __syncthreads();

    int buf = 0;
    for (int k0 = 0; k0 < EE; k0 += 32) {
        const bool more = (k0 + 32 < EE);
        if (more) stage(buf ^ 1, k0 + 32);   // DMA overlaps compute

        const uint32_t* ah = su + buf * GBUF;
        const uint32_t* al = ah + GKA;
        const uint32_t* bh = su + buf * GBUF + 2 * GKA;
        const uint32_t* bl = bh + GKB;

        #pragma unroll
        for (int ks = 0; ks < 2; ks++) {     // two k16 steps per k0=32
            uint32_t aH[4][4], aL[4][4];
            #pragma unroll
            for (int mf = 0; mf < 4; mf++) {
                const int r0 = (wm + mf * 16 + g) * 20 + ks * 8 + tg;
                const int r1 = r0 + 8 * 20;
                aH[mf][0] = ah[r0];     aH[mf][1] = ah[r1];
                aH[mf][2] = ah[r0 + 4]; aH[mf][3] = ah[r1 + 4];
                aL[mf][0] = al[r0];     aL[mf][1] = al[r1];
                aL[mf][2] = al[r0 + 4]; aL[mf][3] = al[r1 + 4];
            }
            uint32_t bH[8][2], bL[8][2];
            #pragma unroll
            for (int nf = 0; nf < 8; nf++) {
                const int bb = (wn + nf * 8 + g) * 20 + ks * 8 + tg;
                bH[nf][0] = bh[bb]; bH[nf][1] = bh[bb + 4];
                bL[nf][0] = bl[bb]; bL[nf][1] = bl[bb + 4];
            }
            #pragma unroll
            for (int mf = 0; mf < 4; mf++) {
                #pragma unroll
                for (int nf = 0; nf < 8; nf++) {
                    mma_bf16(acc[mf][nf], aH[mf][0], aH[mf][1], aH[mf][2], aH[mf][3],
                             bH[nf][0], bH[nf][1]);
                    mma_bf16(acc[mf][nf], aL[mf][0], aL[mf][1], aL[mf][2], aL[mf][3],
                             bH[nf][0], bH[nf][1]);
                    mma_bf16(acc[mf][nf], aH[mf][0], aH[mf][1], aH[mf][2], aH[mf][3],
                             bL[nf][0], bL[nf][1]);
                }
            }
        }
        if (more) CP_WAIT0();
        __syncthreads();
        buf ^= 1;
    }

    #pragma unroll
    for (int mf = 0; mf < 4; mf++) {
        const int row = rowBase + wm + mf * 16 + g;
        #pragma unroll
        for (int nf = 0; nf < 8; nf++) {
            const int col = colBase + wn + nf * 8 + 2 * tg;
            const float b0 = bias[col];
            const float b1 = bias[col + 1];
            const float o0 = acc[mf][nf][0] + b0, o1 = acc[mf][nf][1] + b1;
            const float o2 = acc[mf][nf][2] + b0, o3 = acc[mf][nf][3] + b1;
            if (obf) {
                if (row < M) {
                    const uint32_t hp = pack_bf16(o0, o1);
                    const uint32_t lp = pack_bf16(o0 - bf16lo_f(hp), o1 - bf16hi_f(hp));
                    const size_t off = (size_t)row * EE + col;
                    *(uint32_t*)(ch + off) = hp;
                    *(uint32_t*)(cl + off) = lp;
                }
                if (row + 8 < M) {
                    const uint32_t hp = pack_bf16(o2, o3);
                    const uint32_t lp = pack_bf16(o2 - bf16lo_f(hp), o3 - bf16hi_f(hp));
                    const size_t off = (size_t)(row + 8) * EE + col;
                    *(uint32_t*)(ch + off) = hp;
                    *(uint32_t*)(cl + off) = lp;
                }
            } else {
                if (row < M)
                    *(float2*)(Cf + (size_t)row * EE + col) = make_float2(o0, o1);
                if (row + 8 < M)
                    *(float2*)(Cf + (size_t)(row + 8) * EE + col) = make_float2(o2, o3);
            }
        }
    }
}

// ---------------------------------------------------------------------------
// Flash attention, full 3xBF16 (m16n8k16) for S = QK^T and O += P V.
// Q/K/V arrive pre-split bf16 hi/lo [token][d] from the projection GEMMs.
// V is transposed to [d][token] in smem per k-tile (byte_perm), staging
// buffer aliased into the then-dead P region.
// Block: 128 q-rows; k-tiles of 64. 8 warps; warp w owns q rows [16w,16w+16).
// smem (u32): Qh/Ql 128x36, Kh/Kl 64x36, Vth/Vtl 64x36, Ph/Pl 128x36
//           = 27648 u32 = 110592 B -> 2 CTAs/SM.
// ---------------------------------------------------------------------------
#define FQB 128
#define FKB 64
#define FS 36            // u32 row stride everywhere (banks 4g+tg distinct)
#define O_QH 0
#define O_QL (O_QH + 128 * FS)
#define O_KH (O_QL + 128 * FS)
#define O_KL (O_KH + 64 * FS)
#define O_VTH (O_KL + 64 * FS)
#define O_VTL (O_VTH + 64 * FS)
#define O_PH (O_VTL + 64 * FS)
#define O_PL (O_PH + 128 * FS)
#define O_VSH O_PH            // V staging aliases P (dead at staging time)
#define O_VSL (O_PH + 2048)
#define FSMEM_U32 (O_PL + 128 * FS)   // 27648
#define FSMEM_BYTES (FSMEM_U32 * 4)   // 110592

__global__ __launch_bounds__(256, 2) void flash_attn_bf16(
    const __nv_bfloat16* __restrict__ qh, const __nv_bfloat16* __restrict__ ql,
    const __nv_bfloat16* __restrict__ kh, const __nv_bfloat16* __restrict__ kl,
    const __nv_bfloat16* __restrict__ vh, const __nv_bfloat16* __restrict__ vl,
    __nv_bfloat16* __restrict__ oh, __nv_bfloat16* __restrict__ ol)
{
    extern __shared__ uint32_t su[];
    const uint32_t sbase = smem_u32(su);

    const int tid  = threadIdx.x;
    const int lane = tid & 31;
    const int wid  = tid >> 5;       // 0..7
    const int g    = lane >> 2;      // 0..7
    const int tg   = lane & 3;       // 0..3

    const int bh = blockIdx.x;
    const int b = bh >> 4;
    const int h = bh & 15;
    const int q0 = blockIdx.y * FQB;

    const size_t base = (size_t)b * TT * EE + (size_t)h * DD;

    // ---- stage Q tile (bf16 hi/lo): 128 rows x 8 chunks each ----
    #pragma unroll
    for (int i = 0; i < 4; i++) {
        const int idx = tid + i * 256;
        const int r = idx >> 3;
        const int c = idx & 7;
        const int gr = q0 + r;
        const size_t go = base + (size_t)gr * EE + c * 8;
        const uint32_t dst = sbase + (uint32_t)(O_QH + r * FS + c * 4) * 4;
        cp16(dst, qh + go, gr < TT);
        cp16(dst + (uint32_t)(O_QL - O_QH) * 4, ql + go, gr < TT);
    }
    CP_COMMIT();

    float m0 = -1e30f, m1 = -1e30f, l0 = 0.f, l1 = 0.f;
    float oacc[8][4];
    #pragma unroll
    for (int nf = 0; nf < 8; nf++)
        #pragma unroll
        for (int c = 0; c < 4; c++) oacc[nf][c] = 0.f;

    const int row0 = 16 * wid + g;   // local q rows owned by this lane
    const int row1 = row0 + 8;

    const uint32_t* sQh = su + O_QH;
    const uint32_t* sQl = su + O_QL;
    const uint32_t* sKh = su + O_KH;
    const uint32_t* sKl = su + O_KL;
    const uint32_t* sVth = su + O_VTH;
    const uint32_t* sVtl = su + O_VTL;
    uint32_t* sPh = su + O_PH;
    uint32_t* sPl = su + O_PL;

    const int nkt = (TT + FKB - 1) / FKB;   // 10
    for (int kt = 0; kt < nkt; kt++) {
        const int kbase = kt * FKB;
        __syncthreads();   // prev-tile readers of K/Vt/P done

        // ---- stage K (hi/lo, stride FS) and V (hi/lo, staging stride 32) ----
        #pragma unroll
        for (int i = 0; i < 2; i++) {
            const int idx = tid + i * 256;
            const int r = idx >> 3;
            const int c = idx & 7;
            const int gr = kbase + r;
            const size_t go = base + (size_t)gr * EE + c * 8;
            const uint32_t kdst = sbase + (uint32_t)(O_KH + r * FS + c * 4) * 4;
            cp16(kdst, kh + go, gr < TT);
            cp16(kdst + (uint32_t)(O_KL - O_KH) * 4, kl + go, gr < TT);
            const uint32_t vdst = sbase + (uint32_t)(O_VSH + r * 32 + c * 4) * 4;
            cp16(vdst, vh + go, gr < TT);
            cp16(vdst + (uint32_t)(O_VSL - O_VSH) * 4, vl + go, gr < TT);
        }
        CP_COMMIT();
        CP_WAIT0();          // also covers the Q group on iter 0
        __syncthreads();

        // ---- transpose V: [token][d] -> Vt [d][token] (bf16 via byte_perm) ----
        #pragma unroll
        for (int i = 0; i < 16; i++) {
            const int idx = tid + i * 256;        // 4096 outputs (hi then lo)
            const uint32_t* stg = (idx < 2048) ? (su + O_VSH) : (su + O_VSL);
            uint32_t* vt = (idx < 2048) ? (su + O_VTH) : (su + O_VTL);
            const int j = idx & 2047;
            const int d = j >> 5;
            const int t = j & 31;
            const uint32_t w0 = stg[(2 * t) * 32 + (d >> 1)];
            const uint32_t w1 = stg[(2 * t + 1) * 32 + (d >> 1)];
            vt[d * FS + t] = __byte_perm(w0, w1, (d & 1) ? 0x7632 : 0x5410);
        }
        __syncthreads();

        // ---- S = Q K^T (3xBF16), warp computes 16 rows x 64 keys ----
        float sacc[8][4];
        #pragma unroll
        for (int nf = 0; nf < 8; nf++)
            #pragma unroll
            for (int c = 0; c < 4; c++) sacc[nf][c] = 0.f;

        #pragma unroll
        for (int ks = 0; ks < 4; ks++) {      // 4 k16 steps over d=64
            const int ar0 = row0 * FS + ks * 8 + tg;
            const int ar1 = ar0 + 8 * FS;
            const uint32_t aH0 = sQh[ar0], aH1 = sQh[ar1];
            const uint32_t aH2 = sQh[ar0 + 4], aH3 = sQh[ar1 + 4];
            const uint32_t aL0 = sQl[ar0], aL1 = sQl[ar1];
            const uint32_t aL2 = sQl[ar0 + 4], aL3 = sQl[ar1 + 4];
            #pragma unroll
            for (int nf = 0; nf < 8; nf++) {
                const int bb = (8 * nf + g) * FS + ks * 8 + tg;
                const uint32_t bH0 = sKh[bb], bH1 = sKh[bb + 4];
                const uint32_t bL0 = sKl[bb], bL1 = sKl[bb + 4];
                mma_bf16(sacc[nf], aH0, aH1, aH2, aH3, bH0, bH1);
                mma_bf16(sacc[nf], aL0, aL1, aL2, aL3, bH0, bH1);
                mma_bf16(sacc[nf], aH0, aH1, aH2, aH3, bL0, bL1);
            }
        }

        // ---- scale + mask + row max ----
        float mx0 = -1e30f, mx1 = -1e30f;
        #pragma unroll
        for (int nf = 0; nf < 8; nf++) {
            const int kc0 = kbase + 8 * nf + 2 * tg;
            const int kc1 = kc0 + 1;
            sacc[nf][0] = (kc0 < TT) ? sacc[nf][0] * 0.125f : -1e30f;
            sacc[nf][1] = (kc1 < TT) ? sacc[nf][1] * 0.125f : -1e30f;
            sacc[nf][2] = (kc0 < TT) ? sacc[nf][2] * 0.125f : -1e30f;
            sacc[nf][3] = (kc1 < TT) ? sacc[nf][3] * 0.125f : -1e30f;
            mx0 = fmaxf(mx0, fmaxf(sacc[nf][0], sacc[nf][1]));
            mx1 = fmaxf(mx1, fmaxf(sacc[nf][2], sacc[nf][3]));
        }
        mx0 = fmaxf(mx0, __shfl_xor_sync(0xffffffffu, mx0, 1));
        mx0 = fmaxf(mx0, __shfl_xor_sync(0xffffffffu, mx0, 2));
        mx1 = fmaxf(mx1, __shfl_xor_sync(0xffffffffu, mx1, 1));
        mx1 = fmaxf(mx1, __shfl_xor_sync(0xffffffffu, mx1, 2));

        const float mn0 = fmaxf(m0, mx0);
        const float mn1 = fmaxf(m1, mx1);
        const float cc0 = __expf(m0 - mn0);
        const float cc1 = __expf(m1 - mn1);
        m0 = mn0; m1 = mn1;

        // ---- P = exp(s - m): bf16 hi/lo to smem, accumulate row sums ----
        float rs0 = 0.f, rs1 = 0.f;
        #pragma unroll
        for (int nf = 0; nf < 8; nf++) {
            const float p0 = __expf(sacc[nf][0] - m0);
            const float p1 = __expf(sacc[nf][1] - m0);
            const float p2 = __expf(sacc[nf][2] - m1);
            const float p3 = __expf(sacc[nf][3] - m1);
            rs0 += p0 + p1;
            rs1 += p2 + p3;
            const int c32 = 4 * nf + tg;     // u32 col for cols (8nf+2tg, +1)
            uint32_t hp = pack_bf16(p0, p1);
            sPh[row0 * FS + c32] = hp;
            sPl[row0 * FS + c32] = pack_bf16(p0 - bf16lo_f(hp), p1 - bf16hi_f(hp));
            hp = pack_bf16(p2, p3);
            sPh[row1 * FS + c32] = hp;
            sPl[row1 * FS + c32] = pack_bf16(p2 - bf16lo_f(hp), p3 - bf16hi_f(hp));
        }
        rs0 += __shfl_xor_sync(0xffffffffu, rs0, 1);
        rs0 += __shfl_xor_sync(0xffffffffu, rs0, 2);
        rs1 += __shfl_xor_sync(0xffffffffu, rs1, 1);
        rs1 += __shfl_xor_sync(0xffffffffu, rs1, 2);
        l0 = l0 * cc0 + rs0;
        l1 = l1 * cc1 + rs1;

        #pragma unroll
        for (int nf = 0; nf < 8; nf++) {
            oacc[nf][0] *= cc0;
            oacc[nf][1] *= cc0;
            oacc[nf][2] *= cc1;
            oacc[nf][3] *= cc1;
        }
        __syncwarp();   // P rows are warp-private: cross-lane visibility

        // ---- O += P V (3xBF16): A = P [q][kc], B = Vt [d][kc] ----
        #pragma unroll
        for (int ks = 0; ks < 4; ks++) {      // 4 k16 steps over kc=64
            const int ar0 = row0 * FS + ks * 8 + tg;
            const int ar1 = ar0 + 8 * FS;
            const uint32_t aH0 = sPh[ar0], aH1 = sPh[ar1];
            const uint32_t aH2 = sPh[ar0 + 4], aH3 = sPh[ar1 + 4];
            const uint32_t aL0 = sPl[ar0], aL1 = sPl[ar1];
            const uint32_t aL2 = sPl[ar0 + 4], aL3 = sPl[ar1 + 4];
            #pragma unroll
            for (int nfd = 0; nfd < 8; nfd++) {
                const int bb = (8 * nfd + g) * FS + ks * 8 + tg;
                const uint32_t bH0 = sVth[bb], bH1 = sVth[bb + 4];
                const uint32_t bL0 = sVtl[bb], bL1 = sVtl[bb + 4];
                mma_bf16(oacc[nfd], aH0, aH1, aH2, aH3, bH0, bH1);
                mma_bf16(oacc[nfd], aL0, aL1, aL2, aL3, bH0, bH1);
                mma_bf16(oacc[nfd], aH0, aH1, aH2, aH3, bL0, bL1);
            }
        }
    }

    // ---- epilogue: normalize + store bf16 hi/lo for the Wo GEMM ----
    const float inv0 = 1.f / l0;
    const float inv1 = 1.f / l1;
    const int gr0 = q0 + row0;
    const int gr1 = q0 + row1;
    #pragma unroll
    for (int nfd = 0; nfd < 8; nfd++) {
        const int col = nfd * 8 + 2 * tg;
        if (gr0 < TT) {
            const float o0 = oacc[nfd][0] * inv0;
            const float o1 = oacc[nfd][1] * inv0;
            const uint32_t hp = pack_bf16(o0, o1);
            const uint32_t lp = pack_bf16(o0 - bf16lo_f(hp), o1 - bf16hi_f(hp));
            const size_t off = base + (size_t)gr0 * EE + col;
            *(uint32_t*)(oh + off) = hp;
            *(uint32_t*)(ol + off) = lp;
        }
        if (gr1 < TT) {
            const float o0 = oacc[nfd][2] * inv1;
            const float o1 = oacc[nfd][3] * inv1;
            const uint32_t hp = pack_bf16(o0, o1);
            const uint32_t lp = pack_bf16(o0 - bf16lo_f(hp), o1 - bf16hi_f(hp));
            const size_t off = base + (size_t)gr1 * EE + col;
            *(uint32_t*)(oh + off) = hp;
            *(uint32_t*)(ol + off) = lp;
        }
    }
}

// ---------------------------------------------------------------------------
// Launch
// ---------------------------------------------------------------------------
extern "C" void kernel_launch(void* const* d_in, const int* in_sizes, int n_in,
                              void* d_out, int out_size)
{
    const float* x  = (const float*)d_in[0];
    const float* Wq = (const float*)d_in[1];
    const float* bq = (const float*)d_in[2];
    const float* Wk = (const float*)d_in[3];
    const float* bk = (const float*)d_in[4];
    const float* Wv = (const float*)d_in[5];
    const float* bv = (const float*)d_in[6];
    const float* Wo = (const float*)d_in[7];
    const float* bo = (const float*)d_in[8];
    float* out = (float*)d_out;

    __nv_bfloat16 *xh, *xl, *qh, *ql, *kh, *kl, *vh, *vl, *ah, *al, *wth, *wtl;
    cudaGetSymbolAddress((void**)&xh, g_xh);
    cudaGetSymbolAddress((void**)&xl, g_xl);
    cudaGetSymbolAddress((void**)&qh, g_qh);
    cudaGetSymbolAddress((void**)&ql, g_ql);
    cudaGetSymbolAddress((void**)&kh, g_kh);
    cudaGetSymbolAddress((void**)&kl, g_kl);
    cudaGetSymbolAddress((void**)&vh, g_vh);
    cudaGetSymbolAddress((void**)&vl, g_vl);
    cudaGetSymbolAddress((void**)&ah, g_ah);
    cudaGetSymbolAddress((void**)&al, g_al);
    cudaGetSymbolAddress((void**)&wth, g_wth);
    cudaGetSymbolAddress((void**)&wtl, g_wtl);

    const int smemG = GSMEM_B;       // 122880
    const int smemF = FSMEM_BYTES;   // 110592
    cudaFuncSetAttribute(gemm_bf16x3, cudaFuncAttributeMaxDynamicSharedMemorySize, smemG);
    cudaFuncSetAttribute(flash_attn_bf16, cudaFuncAttributeMaxDynamicSharedMemorySize, smemF);

    // prep: split x, transpose+split the 4 weight matrices
    const int n4 = MM * EE / 4;
    prep_x<<<(n4 + 255) / 256, 256>>>(x, xh, xl, n4);
    dim3 gridW(EE / 64, EE / 64);         // (16,16)
    const size_t wsz = (size_t)EE * EE;
    prep_w<<<gridW, 256>>>(Wq, wth + 0 * wsz, wtl + 0 * wsz);
    prep_w<<<gridW, 256>>>(Wk, wth + 1 * wsz, wtl + 1 * wsz);
    prep_w<<<gridW, 256>>>(Wv, wth + 2 * wsz, wtl + 2 * wsz);
    prep_w<<<gridW, 256>>>(Wo, wth + 3 * wsz, wtl + 3 * wsz);

    // projections (bf16x3), outputs pre-split bf16 hi/lo for flash
    dim3 gridG(EE / GBN, (MM + 127) / 128);   // (4, 145)
    gemm_bf16x3<<<gridG, 256, smemG>>>(xh, xl, wth + 0 * wsz, wtl + 0 * wsz, bq,
                                       nullptr, qh, ql, 1, MM);
    gemm_bf16x3<<<gridG, 256, smemG>>>(xh, xl, wth + 1 * wsz, wtl + 1 * wsz, bk,
                                       nullptr, kh, kl, 1, MM);
    gemm_bf16x3<<<gridG, 256, smemG>>>(xh, xl, wth + 2 * wsz, wtl + 2 * wsz, bv,
                                       nullptr, vh, vl, 1, MM);

    // attention (full bf16x3)
    dim3 gridA(BB * HH, (TT + FQB - 1) / FQB);  // (512, 5)
    flash_attn_bf16<<<gridA, 256, smemF>>>(qh, ql, kh, kl, vh, vl, ah, al);

    // output projection (fp32 out)
    gemm_bf16x3<<<gridG, 256, smemG>>>(ah, al, wth + 3 * wsz, wtl + 3 * wsz, bo,
                                       out, nullptr, nullptr, 0, MM);
}

// round 17
// speedup vs baseline: 1.3331x; 1.3331x over previous
#include <cuda_runtime.h>
#include <cuda_bf16.h>
#include <math.h>
#include <stdint.h>

// Problem constants
#define BB 32
#define TT 577
#define EE 1024
#define HH 16
#define DD 64
#define MM (BB * TT)   // 18464 rows

// Scratch (alloc-free rule: __device__ globals)
__device__ __nv_bfloat16 g_xh[(size_t)MM * EE];
__device__ __nv_bfloat16 g_xl[(size_t)MM * EE];
__device__ __nv_bfloat16 g_qh[(size_t)MM * EE];
__device__ __nv_bfloat16 g_ql[(size_t)MM * EE];
__device__ __nv_bfloat16 g_kh[(size_t)MM * EE];
__device__ __nv_bfloat16 g_kl[(size_t)MM * EE];
__device__ __nv_bfloat16 g_vh[(size_t)MM * EE];
__device__ __nv_bfloat16 g_vl[(size_t)MM * EE];
__device__ __nv_bfloat16 g_ah[(size_t)MM * EE];
__device__ __nv_bfloat16 g_al[(size_t)MM * EE];
__device__ __nv_bfloat16 g_wth[(size_t)4 * EE * EE];   // W^T hi, [n][k]
__device__ __nv_bfloat16 g_wtl[(size_t)4 * EE * EE];   // W^T lo

// ---------------------------------------------------------------------------
// common helpers
// ---------------------------------------------------------------------------
__device__ __forceinline__ uint32_t smem_u32(const void* p) {
    return (uint32_t)__cvta_generic_to_shared(p);
}
__device__ __forceinline__ void cp16(uint32_t dst, const void* src, bool pred) {
    asm volatile("cp.async.cg.shared.global [%0], [%1], 16, %2;\n"
                 :: "r"(dst), "l"(src), "r"(pred ? 16 : 0));
}
#define CP_COMMIT() asm volatile("cp.async.commit_group;\n" ::: "memory")
#define CP_WAIT0()  asm volatile("cp.async.wait_group 0;\n" ::: "memory")

// pack_bf16(a, b) -> u32 with a in the LOW half (memory-first element)
__device__ __forceinline__ uint32_t pack_bf16(float lo, float hi) {
    uint32_t r;
    asm("cvt.rn.bf16x2.f32 %0, %1, %2;" : "=r"(r) : "f"(hi), "f"(lo));
    return r;
}
__device__ __forceinline__ float bf16lo_f(uint32_t p) { return __uint_as_float(p << 16); }
__device__ __forceinline__ float bf16hi_f(uint32_t p) { return __uint_as_float(p & 0xffff0000u); }

// bf16 m16n8k16 MMA (A row-major, B col-major i.e. [N][K])
__device__ __forceinline__ void mma_bf16(float* acc,
                                         uint32_t a0, uint32_t a1, uint32_t a2, uint32_t a3,
                                         uint32_t b0, uint32_t b1) {
    asm volatile(
        "mma.sync.aligned.m16n8k16.row.col.f32.bf16.bf16.f32 "
        "{%0,%1,%2,%3}, {%4,%5,%6,%7}, {%8,%9}, {%0,%1,%2,%3};\n"
        : "+f"(acc[0]), "+f"(acc[1]), "+f"(acc[2]), "+f"(acc[3])
        : "r"(a0), "r"(a1), "r"(a2), "r"(a3), "r"(b0), "r"(b1));
}

// ---------------------------------------------------------------------------
// prep kernels: fp32 -> bf16 hi/lo splits
// ---------------------------------------------------------------------------
__global__ void prep_x(const float* __restrict__ x,
                       __nv_bfloat16* __restrict__ xh,
                       __nv_bfloat16* __restrict__ xl, int n4) {
    int idx = blockIdx.x * 256 + threadIdx.x;
    if (idx >= n4) return;
    float4 v = ((const float4*)x)[idx];
    uint32_t h0 = pack_bf16(v.x, v.y);
    uint32_t h1 = pack_bf16(v.z, v.w);
    uint32_t l0 = pack_bf16(v.x - bf16lo_f(h0), v.y - bf16hi_f(h0));
    uint32_t l1 = pack_bf16(v.z - bf16lo_f(h1), v.w - bf16hi_f(h1));
    ((uint2*)xh)[idx] = make_uint2(h0, h1);
    ((uint2*)xl)[idx] = make_uint2(l0, l1);
}

// transpose + split: W[k][n] fp32 -> Wt_h/Wt_l [n][k] bf16 (64x64 tiles)
// stride 68 (272 B = 17*16) keeps the float4 staging stores 16B-aligned.
__global__ __launch_bounds__(256) void prep_w(const float* __restrict__ W,
                                              __nv_bfloat16* __restrict__ wth,
                                              __nv_bfloat16* __restrict__ wtl) {
    __shared__ float s[64][68];
    const int tid = threadIdx.x;
    const int k0 = blockIdx.y * 64, n0 = blockIdx.x * 64;
    #pragma unroll
    for (int i = 0; i < 4; i++) {
        const int idx = tid + i * 256;
        const int kk = idx >> 4;
        const int n4 = (idx & 15) * 4;
        *(float4*)&s[kk][n4] = *(const float4*)(W + (size_t)(k0 + kk) * EE + n0 + n4);
    }
    __syncthreads();
    #pragma unroll
    for (int i = 0; i < 4; i++) {
        const int idx = tid + i * 256;
        const int nn = idx >> 4;
        const int k4 = (idx & 15) * 4;
        float s0 = s[k4 + 0][nn], s1 = s[k4 + 1][nn];
        float s2 = s[k4 + 2][nn], s3 = s[k4 + 3][nn];
        uint32_t h0 = pack_bf16(s0, s1), h1 = pack_bf16(s2, s3);
        uint32_t l0 = pack_bf16(s0 - bf16lo_f(h0), s1 - bf16hi_f(h0));
        uint32_t l1 = pack_bf16(s2 - bf16lo_f(h1), s3 - bf16hi_f(h1));
        const size_t off = (size_t)(n0 + nn) * EE + k0 + k4;
        *(uint2*)(wth + off) = make_uint2(h0, h1);
        *(uint2*)(wtl + off) = make_uint2(l0, l1);
    }
}

// ---------------------------------------------------------------------------
// GEMM (3xBF16, mma.sync m16n8k16): C = A @ W + bias
// Output either fp32 (obf=0, Cf) or bf16 hi/lo pairs (obf=1, ch/cl).
// Block tile 128x256, BK=32 elems, 8 warps (2x4), warp tile 64x64.
// smem: packed bf16 (u32), row stride 20 u32. 122880 B, 1 CTA/SM.
// ---------------------------------------------------------------------------
#define GBN 256
#define GKA 2560     // u32 per A hi/lo buffer (128 rows x 20)
#define GKB 5120     // u32 per B hi/lo buffer (256 rows x 20)
#define GBUF (2 * GKA + 2 * GKB)   // 15360 u32 per stage
#define GSMEM_B (2 * GBUF * 4)     // 122880 bytes

__global__ __launch_bounds__(256, 1) void gemm_bf16x3(
    const __nv_bfloat16* __restrict__ agh, const __nv_bfloat16* __restrict__ agl,
    const __nv_bfloat16* __restrict__ bgh, const __nv_bfloat16* __restrict__ bgl,
    const float* __restrict__ bias, float* __restrict__ Cf,
    __nv_bfloat16* __restrict__ ch, __nv_bfloat16* __restrict__ cl,
    int obf, int M)
{
    extern __shared__ uint32_t su[];
    const uint32_t sbase = smem_u32(su);

    const int tid  = threadIdx.x;
    const int lane = tid & 31;
    const int wid  = tid >> 5;        // 0..7
    const int g    = lane >> 2;       // 0..7
    const int tg   = lane & 3;        // 0..3
    const int wm   = (wid >> 2) * 64; // warp row offset (0/64)
    const int wn   = (wid & 3) * 64;  // warp col offset (0/64/128/192)
    const int rowBase = blockIdx.y * 128;
    const int colBase = blockIdx.x * GBN;

    float acc[4][8][4];
    #pragma unroll
    for (int mf = 0; mf < 4; mf++)
        #pragma unroll
        for (int nf = 0; nf < 8; nf++)
            #pragma unroll
            for (int c = 0; c < 4; c++) acc[mf][nf][c] = 0.f;

    auto stage = [&](int buf, int k0) {   // k0 in bf16 elements
        const uint32_t b0 = sbase + (uint32_t)buf * GBUF * 4;
        #pragma unroll
        for (int i = 0; i < 2; i++) {
            const int idx = tid + i * 256;
            const int r = idx >> 2;
            const int c = idx & 3;
            const bool pred = (rowBase + r) < M;
            const size_t go = (size_t)(rowBase + r) * EE + k0 + c * 8;
            const uint32_t dst = b0 + (uint32_t)(r * 20 + c * 4) * 4;
            cp16(dst, agh + go, pred);
            cp16(dst + GKA * 4, agl + go, pred);
        }
        #pragma unroll
        for (int i = 0; i < 4; i++) {
            const int idx = tid + i * 256;
            const int n = idx >> 2;
            const int c = idx & 3;
            const size_t go = (size_t)(colBase + n) * EE + k0 + c * 8;
            const uint32_t dst = b0 + (uint32_t)(2 * GKA + n * 20 + c * 4) * 4;
            cp16(dst, bgh + go, true);
            cp16(dst + GKB * 4, bgl + go, true);
        }
        CP_COMMIT();
    };

    stage(0, 0);
    CP_WAIT0();
    __syncthreads();

    int buf = 0;
    for (int k0 = 0; k0 < EE; k0 += 32) {
        const bool more = (k0 + 32 < EE);
        if (more) stage(buf ^ 1, k0 + 32);   // DMA overlaps compute

        const uint32_t* ah = su + buf * GBUF;
        const uint32_t* al = ah + GKA;
        const uint32_t* bh = su + buf * GBUF + 2 * GKA;
        const uint32_t* bl = bh + GKB;

        #pragma unroll
        for (int ks = 0; ks < 2; ks++) {     // two k16 steps per k0=32
            uint32_t aH[4][4], aL[4][4];
            #pragma unroll
            for (int mf = 0; mf < 4; mf++) {
                const int r0 = (wm + mf * 16 + g) * 20 + ks * 8 + tg;
                const int r1 = r0 + 8 * 20;
                aH[mf][0] = ah[r0];     aH[mf][1] = ah[r1];
                aH[mf][2] = ah[r0 + 4]; aH[mf][3] = ah[r1 + 4];
                aL[mf][0] = al[r0];     aL[mf][1] = al[r1];
                aL[mf][2] = al[r0 + 4]; aL[mf][3] = al[r1 + 4];
            }
            uint32_t bH[8][2], bL[8][2];
            #pragma unroll
            for (int nf = 0; nf < 8; nf++) {
                const int bb = (wn + nf * 8 + g) * 20 + ks * 8 + tg;
                bH[nf][0] = bh[bb]; bH[nf][1] = bh[bb + 4];
                bL[nf][0] = bl[bb]; bL[nf][1] = bl[bb + 4];
            }
            #pragma unroll
            for (int mf = 0; mf < 4; mf++) {
                #pragma unroll
                for (int nf = 0; nf < 8; nf++) {
                    mma_bf16(acc[mf][nf], aH[mf][0], aH[mf][1], aH[mf][2], aH[mf][3],
                             bH[nf][0], bH[nf][1]);
                    mma_bf16(acc[mf][nf], aL[mf][0], aL[mf][1], aL[mf][2], aL[mf][3],
                             bH[nf][0], bH[nf][1]);
                    mma_bf16(acc[mf][nf], aH[mf][0], aH[mf][1], aH[mf][2], aH[mf][3],
                             bL[nf][0], bL[nf][1]);
                }
            }
        }
        if (more) CP_WAIT0();
        __syncthreads();
        buf ^= 1;
    }

    #pragma unroll
    for (int mf = 0; mf < 4; mf++) {
        const int row = rowBase + wm + mf * 16 + g;
        #pragma unroll
        for (int nf = 0; nf < 8; nf++) {
            const int col = colBase + wn + nf * 8 + 2 * tg;
            const float b0 = bias[col];
            const float b1 = bias[col + 1];
            const float o0 = acc[mf][nf][0] + b0, o1 = acc[mf][nf][1] + b1;
            const float o2 = acc[mf][nf][2] + b0, o3 = acc[mf][nf][3] + b1;
            if (obf) {
                if (row < M) {
                    const uint32_t hp = pack_bf16(o0, o1);
                    const uint32_t lp = pack_bf16(o0 - bf16lo_f(hp), o1 - bf16hi_f(hp));
                    const size_t off = (size_t)row * EE + col;
                    *(uint32_t*)(ch + off) = hp;
                    *(uint32_t*)(cl + off) = lp;
                }
                if (row + 8 < M) {
                    const uint32_t hp = pack_bf16(o2, o3);
                    const uint32_t lp = pack_bf16(o2 - bf16lo_f(hp), o3 - bf16hi_f(hp));
                    const size_t off = (size_t)(row + 8) * EE + col;
                    *(uint32_t*)(ch + off) = hp;
                    *(uint32_t*)(cl + off) = lp;
                }
            } else {
                if (row < M)
                    *(float2*)(Cf + (size_t)row * EE + col) = make_float2(o0, o1);
                if (row + 8 < M)
                    *(float2*)(Cf + (size_t)(row + 8) * EE + col) = make_float2(o2, o3);
            }
        }
    }
}

// ---------------------------------------------------------------------------
// Flash attention, full 3xBF16 (m16n8k16) for S = QK^T and O += P V.
// Q/K/V arrive pre-split bf16 hi/lo [token][d] from the projection GEMMs.
// V transposed to Vt [d][token] in smem per k-tile; the transpose maps
// d to lanes (reads become broadcast pairs: conflict-free; writes 4-way).
// Block: 128 q-rows; k-tiles of 64. 8 warps; warp w owns q rows [16w,16w+16).
// smem (u32): Qh/Ql 128x36, Kh/Kl 64x36, Vth/Vtl 64x36, Ph/Pl 128x36
//           = 27648 u32 = 110592 B -> 2 CTAs/SM.
// ---------------------------------------------------------------------------
#define FQB 128
#define FKB 64
#define FS 36            // u32 row stride everywhere (banks 4g+tg distinct)
#define O_QH 0
#define O_QL (O_QH + 128 * FS)
#define O_KH (O_QL + 128 * FS)
#define O_KL (O_KH + 64 * FS)
#define O_VTH (O_KL + 64 * FS)
#define O_VTL (O_VTH + 64 * FS)
#define O_PH (O_VTL + 64 * FS)
#define O_PL (O_PH + 128 * FS)
#define O_VSH O_PH            // V staging aliases P (dead at staging time)
#define O_VSL (O_PH + 2048)
#define FSMEM_U32 (O_PL + 128 * FS)   // 27648
#define FSMEM_BYTES (FSMEM_U32 * 4)   // 110592

__global__ __launch_bounds__(256, 2) void flash_attn_bf16(
    const __nv_bfloat16* __restrict__ qh, const __nv_bfloat16* __restrict__ ql,
    const __nv_bfloat16* __restrict__ kh, const __nv_bfloat16* __restrict__ kl,
    const __nv_bfloat16* __restrict__ vh, const __nv_bfloat16* __restrict__ vl,
    __nv_bfloat16* __restrict__ oh, __nv_bfloat16* __restrict__ ol)
{
    extern __shared__ uint32_t su[];
    const uint32_t sbase = smem_u32(su);

    const int tid  = threadIdx.x;
    const int lane = tid & 31;
    const int wid  = tid >> 5;       // 0..7
    const int g    = lane >> 2;      // 0..7
    const int tg   = lane & 3;       // 0..3

    const int bh = blockIdx.x;
    const int b = bh >> 4;
    const int h = bh & 15;
    const int q0 = blockIdx.y * FQB;

    const size_t base = (size_t)b * TT * EE + (size_t)h * DD;

    // ---- stage Q tile (bf16 hi/lo): 128 rows x 8 chunks each ----
    #pragma unroll
    for (int i = 0; i < 4; i++) {
        const int idx = tid + i * 256;
        const int r = idx >> 3;
        const int c = idx & 7;
        const int gr = q0 + r;
        const size_t go = base + (size_t)gr * EE + c * 8;
        const uint32_t dst = sbase + (uint32_t)(O_QH + r * FS + c * 4) * 4;
        cp16(dst, qh + go, gr < TT);
        cp16(dst + (uint32_t)(O_QL - O_QH) * 4, ql + go, gr < TT);
    }
    CP_COMMIT();

    float m0 = -1e30f, m1 = -1e30f, l0 = 0.f, l1 = 0.f;
    float oacc[8][4];
    #pragma unroll
    for (int nf = 0; nf < 8; nf++)
        #pragma unroll
        for (int c = 0; c < 4; c++) oacc[nf][c] = 0.f;

    const int row0 = 16 * wid + g;   // local q rows owned by this lane
    const int row1 = row0 + 8;

    const uint32_t* sQh = su + O_QH;
    const uint32_t* sQl = su + O_QL;
    const uint32_t* sKh = su + O_KH;
    const uint32_t* sKl = su + O_KL;
    const uint32_t* sVth = su + O_VTH;
    const uint32_t* sVtl = su + O_VTL;
    uint32_t* sPh = su + O_PH;
    uint32_t* sPl = su + O_PL;

    const int nkt = (TT + FKB - 1) / FKB;   // 10
    for (int kt = 0; kt < nkt; kt++) {
        const int kbase = kt * FKB;
        __syncthreads();   // prev-tile readers of K/Vt/P done

        // ---- stage K (hi/lo, stride FS) and V (hi/lo, staging stride 32) ----
        #pragma unroll
        for (int i = 0; i < 2; i++) {
            const int idx = tid + i * 256;
            const int r = idx >> 3;
            const int c = idx & 7;
            const int gr = kbase + r;
            const size_t go = base + (size_t)gr * EE + c * 8;
            const uint32_t kdst = sbase + (uint32_t)(O_KH + r * FS + c * 4) * 4;
            cp16(kdst, kh + go, gr < TT);
            cp16(kdst + (uint32_t)(O_KL - O_KH) * 4, kl + go, gr < TT);
            const uint32_t vdst = sbase + (uint32_t)(O_VSH + r * 32 + c * 4) * 4;
            cp16(vdst, vh + go, gr < TT);
            cp16(vdst + (uint32_t)(O_VSL - O_VSH) * 4, vl + go, gr < TT);
        }
        CP_COMMIT();
        CP_WAIT0();          // also covers the Q group on iter 0
        __syncthreads();

        // ---- transpose V: [token][d] -> Vt [d][token] ----
        // d = j&63 maps to lanes: reads are broadcast pairs (conflict-free),
        // writes 4-way banked. (R16 had d warp-constant -> 32-way read conflicts.)
        #pragma unroll
        for (int i = 0; i < 16; i++) {
            const int idx = tid + i * 256;        // 4096 outputs (hi then lo)
            const uint32_t* stg = (idx < 2048) ? (su + O_VSH) : (su + O_VSL);
            uint32_t* vt = (idx < 2048) ? (su + O_VTH) : (su + O_VTL);
            const int j = idx & 2047;
            const int d = j & 63;
            const int t = j >> 6;
            const uint32_t w0 = stg[(2 * t) * 32 + (d >> 1)];
            const uint32_t w1 = stg[(2 * t + 1) * 32 + (d >> 1)];
            vt[d * FS + t] = __byte_perm(w0, w1, (d & 1) ? 0x7632 : 0x5410);
        }
        __syncthreads();

        // ---- S = Q K^T (3xBF16), warp computes 16 rows x 64 keys ----
        float sacc[8][4];
        #pragma unroll
        for (int nf = 0; nf < 8; nf++)
            #pragma unroll
            for (int c = 0; c < 4; c++) sacc[nf][c] = 0.f;

        #pragma unroll
        for (int ks = 0; ks < 4; ks++) {      // 4 k16 steps over d=64
            const int ar0 = row0 * FS + ks * 8 + tg;
            const int ar1 = ar0 + 8 * FS;
            const uint32_t aH0 = sQh[ar0], aH1 = sQh[ar1];
            const uint32_t aH2 = sQh[ar0 + 4], aH3 = sQh[ar1 + 4];
            const uint32_t aL0 = sQl[ar0], aL1 = sQl[ar1];
            const uint32_t aL2 = sQl[ar0 + 4], aL3 = sQl[ar1 + 4];
            #pragma unroll
            for (int nf = 0; nf < 8; nf++) {
                const int bb = (8 * nf + g) * FS + ks * 8 + tg;
                const uint32_t bH0 = sKh[bb], bH1 = sKh[bb + 4];
                const uint32_t bL0 = sKl[bb], bL1 = sKl[bb + 4];
                mma_bf16(sacc[nf], aH0, aH1, aH2, aH3, bH0, bH1);
                mma_bf16(sacc[nf], aL0, aL1, aL2, aL3, bH0, bH1);
                mma_bf16(sacc[nf], aH0, aH1, aH2, aH3, bL0, bL1);
            }
        }

        // ---- scale + mask + row max ----
        float mx0 = -1e30f, mx1 = -1e30f;
        #pragma unroll
        for (int nf = 0; nf < 8; nf++) {
            const int kc0 = kbase + 8 * nf + 2 * tg;
            const int kc1 = kc0 + 1;
            sacc[nf][0] = (kc0 < TT) ? sacc[nf][0] * 0.125f : -1e30f;
            sacc[nf][1] = (kc1 < TT) ? sacc[nf][1] * 0.125f : -1e30f;
            sacc[nf][2] = (kc0 < TT) ? sacc[nf][2] * 0.125f : -1e30f;
            sacc[nf][3] = (kc1 < TT) ? sacc[nf][3] * 0.125f : -1e30f;
            mx0 = fmaxf(mx0, fmaxf(sacc[nf][0], sacc[nf][1]));
            mx1 = fmaxf(mx1, fmaxf(sacc[nf][2], sacc[nf][3]));
        }
        mx0 = fmaxf(mx0, __shfl_xor_sync(0xffffffffu, mx0, 1));
        mx0 = fmaxf(mx0, __shfl_xor_sync(0xffffffffu, mx0, 2));
        mx1 = fmaxf(mx1, __shfl_xor_sync(0xffffffffu, mx1, 1));
        mx1 = fmaxf(mx1, __shfl_xor_sync(0xffffffffu, mx1, 2));

        const float mn0 = fmaxf(m0, mx0);
        const float mn1 = fmaxf(m1, mx1);
        const float cc0 = __expf(m0 - mn0);
        const float cc1 = __expf(m1 - mn1);
        m0 = mn0; m1 = mn1;

        // ---- P = exp(s - m): bf16 hi/lo to smem, accumulate row sums ----
        float rs0 = 0.f, rs1 = 0.f;
        #pragma unroll
        for (int nf = 0; nf < 8; nf++) {
            const float p0 = __expf(sacc[nf][0] - m0);
            const float p1 = __expf(sacc[nf][1] - m0);
            const float p2 = __expf(sacc[nf][2] - m1);
            const float p3 = __expf(sacc[nf][3] - m1);
            rs0 += p0 + p1;
            rs1 += p2 + p3;
            const int c32 = 4 * nf + tg;     // u32 col for cols (8nf+2tg, +1)
            uint32_t hp = pack_bf16(p0, p1);
            sPh[row0 * FS + c32] = hp;
            sPl[row0 * FS + c32] = pack_bf16(p0 - bf16lo_f(hp), p1 - bf16hi_f(hp));
            hp = pack_bf16(p2, p3);
            sPh[row1 * FS + c32] = hp;
            sPl[row1 * FS + c32] = pack_bf16(p2 - bf16lo_f(hp), p3 - bf16hi_f(hp));
        }
        rs0 += __shfl_xor_sync(0xffffffffu, rs0, 1);
        rs0 += __shfl_xor_sync(0xffffffffu, rs0, 2);
        rs1 += __shfl_xor_sync(0xffffffffu, rs1, 1);
        rs1 += __shfl_xor_sync(0xffffffffu, rs1, 2);
        l0 = l0 * cc0 + rs0;
        l1 = l1 * cc1 + rs1;

        #pragma unroll
        for (int nf = 0; nf < 8; nf++) {
            oacc[nf][0] *= cc0;
            oacc[nf][1] *= cc0;
            oacc[nf][2] *= cc1;
            oacc[nf][3] *= cc1;
        }
        __syncwarp();   // P rows are warp-private: cross-lane visibility

        // ---- O += P V (3xBF16): A = P [q][kc], B = Vt [d][kc] ----
        #pragma unroll
        for (int ks = 0; ks < 4; ks++) {      // 4 k16 steps over kc=64
            const int ar0 = row0 * FS + ks * 8 + tg;
            const int ar1 = ar0 + 8 * FS;
            const uint32_t aH0 = sPh[ar0], aH1 = sPh[ar1];
            const uint32_t aH2 = sPh[ar0 + 4], aH3 = sPh[ar1 + 4];
            const uint32_t aL0 = sPl[ar0], aL1 = sPl[ar1];
            const uint32_t aL2 = sPl[ar0 + 4], aL3 = sPl[ar1 + 4];
            #pragma unroll
            for (int nfd = 0; nfd < 8; nfd++) {
                const int bb = (8 * nfd + g) * FS + ks * 8 + tg;
                const uint32_t bH0 = sVth[bb], bH1 = sVth[bb + 4];
                const uint32_t bL0 = sVtl[bb], bL1 = sVtl[bb + 4];
                mma_bf16(oacc[nfd], aH0, aH1, aH2, aH3, bH0, bH1);
                mma_bf16(oacc[nfd], aL0, aL1, aL2, aL3, bH0, bH1);
                mma_bf16(oacc[nfd], aH0, aH1, aH2, aH3, bL0, bL1);
            }
        }
    }

    // ---- epilogue: normalize + store bf16 hi/lo for the Wo GEMM ----
    const float inv0 = 1.f / l0;
    const float inv1 = 1.f / l1;
    const int gr0 = q0 + row0;
    const int gr1 = q0 + row1;
    #pragma unroll
    for (int nfd = 0; nfd < 8; nfd++) {
        const int col = nfd * 8 + 2 * tg;
        if (gr0 < TT) {
            const float o0 = oacc[nfd][0] * inv0;
            const float o1 = oacc[nfd][1] * inv0;
            const uint32_t hp = pack_bf16(o0, o1);
            const uint32_t lp = pack_bf16(o0 - bf16lo_f(hp), o1 - bf16hi_f(hp));
            const size_t off = base + (size_t)gr0 * EE + col;
            *(uint32_t*)(oh + off) = hp;
            *(uint32_t*)(ol + off) = lp;
        }
        if (gr1 < TT) {
            const float o0 = oacc[nfd][2] * inv1;
            const float o1 = oacc[nfd][3] * inv1;
            const uint32_t hp = pack_bf16(o0, o1);
            const uint32_t lp = pack_bf16(o0 - bf16lo_f(hp), o1 - bf16hi_f(hp));
            const size_t off = base + (size_t)gr1 * EE + col;
            *(uint32_t*)(oh + off) = hp;
            *(uint32_t*)(ol + off) = lp;
        }
    }
}

// ---------------------------------------------------------------------------
// Launch
// ---------------------------------------------------------------------------
extern "C" void kernel_launch(void* const* d_in, const int* in_sizes, int n_in,
                              void* d_out, int out_size)
{
    const float* x  = (const float*)d_in[0];
    const float* Wq = (const float*)d_in[1];
    const float* bq = (const float*)d_in[2];
    const float* Wk = (const float*)d_in[3];
    const float* bk = (const float*)d_in[4];
    const float* Wv = (const float*)d_in[5];
    const float* bv = (const float*)d_in[6];
    const float* Wo = (const float*)d_in[7];
    const float* bo = (const float*)d_in[8];
    float* out = (float*)d_out;

    __nv_bfloat16 *xh, *xl, *qh, *ql, *kh, *kl, *vh, *vl, *ah, *al, *wth, *wtl;
    cudaGetSymbolAddress((void**)&xh, g_xh);
    cudaGetSymbolAddress((void**)&xl, g_xl);
    cudaGetSymbolAddress((void**)&qh, g_qh);
    cudaGetSymbolAddress((void**)&ql, g_ql);
    cudaGetSymbolAddress((void**)&kh, g_kh);
    cudaGetSymbolAddress((void**)&kl, g_kl);
    cudaGetSymbolAddress((void**)&vh, g_vh);
    cudaGetSymbolAddress((void**)&vl, g_vl);
    cudaGetSymbolAddress((void**)&ah, g_ah);
    cudaGetSymbolAddress((void**)&al, g_al);
    cudaGetSymbolAddress((void**)&wth, g_wth);
    cudaGetSymbolAddress((void**)&wtl, g_wtl);

    const int smemG = GSMEM_B;       // 122880
    const int smemF = FSMEM_BYTES;   // 110592
    cudaFuncSetAttribute(gemm_bf16x3, cudaFuncAttributeMaxDynamicSharedMemorySize, smemG);
    cudaFuncSetAttribute(flash_attn_bf16, cudaFuncAttributeMaxDynamicSharedMemorySize, smemF);

    // prep: split x, transpose+split the 4 weight matrices
    const int n4 = MM * EE / 4;
    prep_x<<<(n4 + 255) / 256, 256>>>(x, xh, xl, n4);
    dim3 gridW(EE / 64, EE / 64);         // (16,16)
    const size_t wsz = (size_t)EE * EE;
    prep_w<<<gridW, 256>>>(Wq, wth + 0 * wsz, wtl + 0 * wsz);
    prep_w<<<gridW, 256>>>(Wk, wth + 1 * wsz, wtl + 1 * wsz);
    prep_w<<<gridW, 256>>>(Wv, wth + 2 * wsz, wtl + 2 * wsz);
    prep_w<<<gridW, 256>>>(Wo, wth + 3 * wsz, wtl + 3 * wsz);

    // projections (bf16x3), outputs pre-split bf16 hi/lo for flash
    dim3 gridG(EE / GBN, (MM + 127) / 128);   // (4, 145)
    gemm_bf16x3<<<gridG, 256, smemG>>>(xh, xl, wth + 0 * wsz, wtl + 0 * wsz, bq,
                                       nullptr, qh, ql, 1, MM);
    gemm_bf16x3<<<gridG, 256, smemG>>>(xh, xl, wth + 1 * wsz, wtl + 1 * wsz, bk,
                                       nullptr, kh, kl, 1, MM);
    gemm_bf16x3<<<gridG, 256, smemG>>>(xh, xl, wth + 2 * wsz, wtl + 2 * wsz, bv,
                                       nullptr, vh, vl, 1, MM);

    // attention (full bf16x3)
    dim3 gridA(BB * HH, (TT + FQB - 1) / FQB);  // (512, 5)
    flash_attn_bf16<<<gridA, 256, smemF>>>(qh, ql, kh, kl, vh, vl, ah, al);

    // output projection (fp32 out)
    gemm_bf16x3<<<gridG, 256, smemG>>>(ah, al, wth + 3 * wsz, wtl + 3 * wsz, bo,
                                       out, nullptr, nullptr, 0, MM);
}